// round 2
// baseline (speedup 1.0000x reference)
#include <cuda_runtime.h>
#include <cstdint>

#define BB 256
#define TT 1024
#define HH 128
#define II 19

// Scratch (device globals; no runtime allocation allowed)
__device__ float g_pre[BB * TT * HH];   // pre-activations for current layer
__device__ float g_out1[BB * TT * HH];  // layer-0 hidden outputs

typedef unsigned long long ull;

// packed f32x2 FMA: d = a*b + c elementwise on two packed fp32 lanes
__device__ __forceinline__ ull ffma2(ull a, ull b, ull c) {
    ull d;
    asm("fma.rn.f32x2 %0, %1, %2, %3;" : "=l"(d) : "l"(a), "l"(b), "l"(c));
    return d;
}

__device__ __forceinline__ float hsum2(ull a) {
    float x, y;
    asm("mov.b64 {%0, %1}, %2;" : "=f"(x), "=f"(y) : "l"(a));
    return x + y;
}

// tanh via fast exp: ~1e-6 abs error, saturates correctly at +/-1
__device__ __forceinline__ float fast_tanh(float x) {
    float e = __expf(2.0f * x);
    return 1.0f - __fdividef(2.0f, e + 1.0f);
}

// ---------------------------------------------------------------------------
// proj0: pre = x @ W_ih0^T + (b_ih0 + b_hh0).  x:[B,T,19], W:[128,19]
// block = 128 threads (one output neuron each), ROWS0 (b,t) rows per block.
// ---------------------------------------------------------------------------
#define ROWS0 8
__global__ void __launch_bounds__(128) proj0_kernel(
    const float* __restrict__ x,
    const float* __restrict__ Wih,
    const float* __restrict__ bih,
    const float* __restrict__ bhh)
{
    __shared__ float xs[ROWS0 * II];
    const int j   = threadIdx.x;
    const int blk = blockIdx.x;

    // W row j + fused bias in registers
    float w[II];
#pragma unroll
    for (int i = 0; i < II; i++) w[i] = Wih[j * II + i];
    const float bias = bih[j] + bhh[j];

    // x rows for this block are contiguous: copy flat
    const float* src = x + (size_t)blk * ROWS0 * II;
    for (int i = j; i < ROWS0 * II; i += 128) xs[i] = src[i];
    __syncthreads();

#pragma unroll
    for (int r = 0; r < ROWS0; r++) {
        float acc = bias;
#pragma unroll
        for (int i = 0; i < II; i++) acc += xs[r * II + i] * w[i];
        g_pre[((size_t)blk * ROWS0 + r) * HH + j] = acc;
    }
}

// ---------------------------------------------------------------------------
// proj1: pre = out1 @ W_ih1^T + (b_ih1 + b_hh1).  out1:[B*T,128], W:[128,128]
// block = 128 threads (neuron j), ROWS1 rows per block.
// W row held in 64 packed f32x2 registers; inputs staged in shared,
// broadcast-read as LDS.128; packed-over-K FFMA2.
// ---------------------------------------------------------------------------
#define ROWS1 16
__global__ void __launch_bounds__(128) proj1_kernel(
    const float* __restrict__ Wih,
    const float* __restrict__ bih,
    const float* __restrict__ bhh)
{
    __shared__ __align__(16) float in_s[ROWS1 * HH];
    const int j   = threadIdx.x;
    const int blk = blockIdx.x;

    // W_ih1 row j as 64 packed pairs
    ull w[64];
    {
        const ulonglong2* wr = (const ulonglong2*)(Wih + j * HH);
#pragma unroll
        for (int q = 0; q < 32; q++) {
            ulonglong2 t = wr[q];
            w[2 * q]     = t.x;
            w[2 * q + 1] = t.y;
        }
    }
    const float bias = bih[j] + bhh[j];

    // cooperative flat copy of ROWS1 contiguous input rows
    {
        const float4* src = (const float4*)(g_out1 + (size_t)blk * ROWS1 * HH);
        float4*       dst = (float4*)in_s;
        for (int i = j; i < ROWS1 * HH / 4; i += 128) dst[i] = src[i];
    }
    __syncthreads();

#pragma unroll 1
    for (int r = 0; r < ROWS1; r++) {
        const ulonglong2* h2 = (const ulonglong2*)(in_s + r * HH);
        ull a0 = 0, a1 = 0, a2 = 0, a3 = 0;
#pragma unroll
        for (int q = 0; q < 16; q++) {
            ulonglong2 v0 = h2[2 * q];
            ulonglong2 v1 = h2[2 * q + 1];
            a0 = ffma2(v0.x, w[4 * q],     a0);
            a1 = ffma2(v0.y, w[4 * q + 1], a1);
            a2 = ffma2(v1.x, w[4 * q + 2], a2);
            a3 = ffma2(v1.y, w[4 * q + 3], a3);
        }
        float s = bias + hsum2(a0) + hsum2(a1) + hsum2(a2) + hsum2(a3);
        g_pre[((size_t)blk * ROWS1 + r) * HH + j] = s;
    }
}

// ---------------------------------------------------------------------------
// scan: h_t = tanh(pre_t + W_hh h_{t-1}) for one batch row per CTA.
// 256 CTAs x 128 threads. W_hh row j in 64 packed registers. Double-buffered
// h in shared, one barrier per step, distance-2 prefetch of pre.
// outp == nullptr -> write g_out1 (layer 0), else write outp (layer 1).
// ---------------------------------------------------------------------------
__global__ void __launch_bounds__(128, 2) scan_kernel(
    const float* __restrict__ Whh,
    float* __restrict__ outp)
{
    __shared__ __align__(16) float hs[2][HH];
    const int j = threadIdx.x;
    const int b = blockIdx.x;

    ull w[64];
    {
        const ulonglong2* wr = (const ulonglong2*)(Whh + j * HH);
#pragma unroll
        for (int q = 0; q < 32; q++) {
            ulonglong2 t = wr[q];
            w[2 * q]     = t.x;
            w[2 * q + 1] = t.y;
        }
    }

    float* out = outp ? outp : g_out1;
    const float* prow = g_pre + (size_t)b * TT * HH + j;
    float*       orow = out   + (size_t)b * TT * HH + j;

    hs[0][j] = 0.0f;
    hs[1][j] = 0.0f;
    __syncthreads();

    float p0 = prow[0];
    float p1 = prow[HH];
    int cur = 0;

#pragma unroll 1
    for (int t = 0; t < TT; t++) {
        // prefetch pre for t+2 (independent of the h chain)
        float pnext = (t + 2 < TT) ? prow[(size_t)(t + 2) * HH] : 0.0f;

        const ulonglong2* h2 = (const ulonglong2*)hs[cur];
        ull a0 = 0, a1 = 0, a2 = 0, a3 = 0;
#pragma unroll
        for (int q = 0; q < 16; q++) {
            ulonglong2 v0 = h2[2 * q];
            ulonglong2 v1 = h2[2 * q + 1];
            a0 = ffma2(v0.x, w[4 * q],     a0);
            a1 = ffma2(v0.y, w[4 * q + 1], a1);
            a2 = ffma2(v1.x, w[4 * q + 2], a2);
            a3 = ffma2(v1.y, w[4 * q + 3], a3);
        }
        float s = p0 + hsum2(a0) + hsum2(a1) + hsum2(a2) + hsum2(a3);
        float hn = fast_tanh(s);

        orow[(size_t)t * HH] = hn;
        hs[cur ^ 1][j] = hn;
        __syncthreads();

        p0 = p1;
        p1 = pnext;
        cur ^= 1;
    }
}

// ---------------------------------------------------------------------------
extern "C" void kernel_launch(void* const* d_in, const int* in_sizes, int n_in,
                              void* d_out, int out_size)
{
    const float* x     = (const float*)d_in[0];
    const float* Wih0  = (const float*)d_in[1];
    const float* Whh0  = (const float*)d_in[2];
    const float* bih0  = (const float*)d_in[3];
    const float* bhh0  = (const float*)d_in[4];
    const float* Wih1  = (const float*)d_in[5];
    const float* Whh1  = (const float*)d_in[6];
    const float* bih1  = (const float*)d_in[7];
    const float* bhh1  = (const float*)d_in[8];
    float* out = (float*)d_out;

    // layer 0
    proj0_kernel<<<BB * TT / ROWS0, 128>>>(x, Wih0, bih0, bhh0);
    scan_kernel<<<BB, 128>>>(Whh0, nullptr);

    // layer 1
    proj1_kernel<<<BB * TT / ROWS1, 128>>>(Wih1, bih1, bhh1);
    scan_kernel<<<BB, 128>>>(Whh1, out);
}